// round 14
// baseline (speedup 1.0000x reference)
#include <cuda_runtime.h>

// out[b,t,w,c] = x[b, t+w-9, c], zero-padded in t.  B=32, T=4096, W=19, C=30.
// Identity: out row (b,t) [570 floats] == contiguous x slice starting at
// flat element (b*4096 + t - 9)*30, with pad rows zeroed.
//
// Champion structure, A/B probe: default-policy stores instead of .cs
// (the only variable never isolated on this structure). Everything else
// identical to the 49.15us champion.

#define T_DIM   4096
#define C_DIM   30
#define ROW     570             // W*C
#define PAD     9
#define TT      64              // t-rows per block
#define SROWS   (TT + 2*PAD)    // 82
#define SFLOATS (SROWS * C_DIM) // 2460
#define THREADS 480
#define ITERS   38              // TT*ROW/2 / THREADS = 18240/480

__device__ __forceinline__ void stg_v2(float2* p, float2 v) {
    asm volatile("st.global.v2.f32 [%0], {%1,%2};"
                 :: "l"(p), "f"(v.x), "f"(v.y) : "memory");
}

// cp.async 8B with runtime src-size: src_bytes==0 -> zero-fill destination.
__device__ __forceinline__ void cp_async_8_zfill(unsigned smem_addr,
                                                 const void* gptr,
                                                 unsigned src_bytes) {
    asm volatile("cp.async.ca.shared.global [%0], [%1], 8, %2;"
                 :: "r"(smem_addr), "l"(gptr), "r"(src_bytes) : "memory");
}

__global__ __launch_bounds__(THREADS)
void overlap_window_defstore_kernel(const float* __restrict__ x,
                                    float2* __restrict__ out2) {
    __shared__ float s[SFLOATS];

    const int tile = blockIdx.x;            // 0 .. 2047
    const int tpb  = T_DIM / TT;            // 64 tiles per batch
    const int b    = tile / tpb;
    const int t0   = (tile - b * tpb) * TT;
    const int tid  = threadIdx.x;

    // ---- stage x[(b*4096 + t0 - 9)*30 ... +2460) into smem via cp.async ----
    const int lo = (t0 == 0) ? (PAD * C_DIM) : 0;
    const int hi_raw = (T_DIM - t0 + PAD) * C_DIM;
    const int hi = hi_raw < SFLOATS ? hi_raw : SFLOATS;
    const int gbase = (b * T_DIM + t0 - PAD) * C_DIM;  // even
    const float2* __restrict__ x2 = (const float2*)x;

    unsigned s_base;
    asm("{ .reg .u64 t; cvta.to.shared.u64 t, %1; cvt.u32.u64 %0, t; }"
        : "=r"(s_base) : "l"((const void*)s));

    #pragma unroll
    for (int k = 0; k < (SFLOATS / 2 + THREADS - 1) / THREADS; k++) {
        int idx2 = tid + k * THREADS;
        if (idx2 < SFLOATS / 2) {
            int i = idx2 * 2;
            unsigned nbytes = (i >= lo && i < hi) ? 8u : 0u;
            cp_async_8_zfill(s_base + (unsigned)idx2 * 8u,
                             (const void*)&x2[(gbase >> 1) + idx2], nbytes);
        }
    }
    asm volatile("cp.async.commit_group;" ::: "memory");
    asm volatile("cp.async.wait_group 0;" ::: "memory");
    __syncthreads();

    // ---- emit 18240 float2s; float2 index q = tid + k*480, element e = 2q ----
    float2* __restrict__ out_tile = out2 + ((size_t)(b * T_DIM + t0) * ROW) / 2;

    int e   = tid * 2;                  // 0..958
    int r   = (e >= ROW) ? 1 : 0;
    int rem = e - r * ROW;

    #pragma unroll
    for (int k = 0; k < ITERS; k++) {
        int src = r * C_DIM + rem;      // even -> 8B aligned, conflict-free
        float2 v = *(const float2*)&s[src];
        stg_v2(&out_tile[tid + k * THREADS], v);

        rem += 960 - ROW;               // += 390
        r   += 1;
        if (rem >= ROW) { rem -= ROW; r += 1; }
    }
}

extern "C" void kernel_launch(void* const* d_in, const int* in_sizes, int n_in,
                              void* d_out, int out_size) {
    const float* x = (const float*)d_in[0];
    float2* out2 = (float2*)d_out;
    const int blocks = 32 * (T_DIM / TT);   // 2048
    overlap_window_defstore_kernel<<<blocks, THREADS>>>(x, out2);
}

// round 15
// speedup vs baseline: 1.1250x; 1.1250x over previous
#include <cuda_runtime.h>

// out[b,t,w,c] = x[b, t+w-9, c], zero-padded in t.  B=32, T=4096, W=19, C=30.
// Identity: out row (b,t) [570 floats] == contiguous x slice starting at
// flat element (b*4096 + t - 9)*30, with pad rows zeroed.
//
// FINAL CHAMPION (roofline-converged): 314.3 MB moved at ~6.4 TB/s sustained
// (~80% of 8 TB/s spec) — verified attainable mixed R+W DRAM bound via full
// ablation: store width (neutral), store policy (.cs REQUIRED: +12% vs
// default, +13% vs .wt, +8% vs bulk-store), staging path (neutral), tile
// size (TT=64 best), occupancy (neutral), index math (never binding).
// Structure: cp.async zero-fill staging into smem, conflict-free float2 emit
// (8B lane stride), exact-divide fully unrolled loop (480 thr x 38 iters =
// 18240 float2/tile), .cs evict-first streaming stores.

#define T_DIM   4096
#define C_DIM   30
#define ROW     570             // W*C
#define PAD     9
#define TT      64              // t-rows per block
#define SROWS   (TT + 2*PAD)    // 82
#define SFLOATS (SROWS * C_DIM) // 2460
#define THREADS 480
#define ITERS   38              // TT*ROW/2 / THREADS = 18240/480

__device__ __forceinline__ void stg_cs_v2(float2* p, float2 v) {
    asm volatile("st.global.cs.v2.f32 [%0], {%1,%2};"
                 :: "l"(p), "f"(v.x), "f"(v.y) : "memory");
}

// cp.async 8B with runtime src-size: src_bytes==0 -> zero-fill destination.
__device__ __forceinline__ void cp_async_8_zfill(unsigned smem_addr,
                                                 const void* gptr,
                                                 unsigned src_bytes) {
    asm volatile("cp.async.ca.shared.global [%0], [%1], 8, %2;"
                 :: "r"(smem_addr), "l"(gptr), "r"(src_bytes) : "memory");
}

__global__ __launch_bounds__(THREADS)
void overlap_window_champion_kernel(const float* __restrict__ x,
                                    float2* __restrict__ out2) {
    __shared__ float s[SFLOATS];

    const int tile = blockIdx.x;            // 0 .. 2047
    const int tpb  = T_DIM / TT;            // 64 tiles per batch
    const int b    = tile / tpb;
    const int t0   = (tile - b * tpb) * TT;
    const int tid  = threadIdx.x;

    // ---- stage x[(b*4096 + t0 - 9)*30 ... +2460) into smem via cp.async ----
    // smem element-pair idx2 holds x flat elements (gbase + 2*idx2, +1);
    // valid iff lo <= 2*idx2 < hi (outside -> zero-fill via src_bytes = 0).
    const int lo = (t0 == 0) ? (PAD * C_DIM) : 0;
    const int hi_raw = (T_DIM - t0 + PAD) * C_DIM;
    const int hi = hi_raw < SFLOATS ? hi_raw : SFLOATS;
    const int gbase = (b * T_DIM + t0 - PAD) * C_DIM;  // even
    const float2* __restrict__ x2 = (const float2*)x;

    unsigned s_base;
    asm("{ .reg .u64 t; cvta.to.shared.u64 t, %1; cvt.u32.u64 %0, t; }"
        : "=r"(s_base) : "l"((const void*)s));

    #pragma unroll
    for (int k = 0; k < (SFLOATS / 2 + THREADS - 1) / THREADS; k++) {
        int idx2 = tid + k * THREADS;
        if (idx2 < SFLOATS / 2) {
            int i = idx2 * 2;
            unsigned nbytes = (i >= lo && i < hi) ? 8u : 0u;
            cp_async_8_zfill(s_base + (unsigned)idx2 * 8u,
                             (const void*)&x2[(gbase >> 1) + idx2], nbytes);
        }
    }
    asm volatile("cp.async.commit_group;" ::: "memory");
    asm volatile("cp.async.wait_group 0;" ::: "memory");
    __syncthreads();

    // ---- emit 18240 float2s; float2 index q = tid + k*480, element e = 2q ----
    // output row r = e/570, rem = e - 570r (even); smem source = r*30 + rem.
    // e advances by 960 per iter: rem += 390 (mod 570), r += 1 or 2.
    float2* __restrict__ out_tile = out2 + ((size_t)(b * T_DIM + t0) * ROW) / 2;

    int e   = tid * 2;                  // 0..958
    int r   = (e >= ROW) ? 1 : 0;
    int rem = e - r * ROW;

    #pragma unroll
    for (int k = 0; k < ITERS; k++) {
        int src = r * C_DIM + rem;      // even -> 8B aligned, conflict-free
        float2 v = *(const float2*)&s[src];
        stg_cs_v2(&out_tile[tid + k * THREADS], v);

        rem += 960 - ROW;               // += 390
        r   += 1;
        if (rem >= ROW) { rem -= ROW; r += 1; }
    }
}

extern "C" void kernel_launch(void* const* d_in, const int* in_sizes, int n_in,
                              void* d_out, int out_size) {
    const float* x = (const float*)d_in[0];
    float2* out2 = (float2*)d_out;
    const int blocks = 32 * (T_DIM / TT);   // 2048
    overlap_window_champion_kernel<<<blocks, THREADS>>>(x, out2);
}